// round 17
// baseline (speedup 1.0000x reference)
#include <cuda_runtime.h>
#include <cuda_fp16.h>
#include <math.h>

#define BATCH 128
#define OUT   256
#define MB    8       // M branches
#define INS   512     // inner size
#define TI    16      // batch tile
#define TB    16      // out tile
#define KMH   384     // k in [0,384): MUFU f16x2 tanh path
#define KTB   128     // k in [384,512): smem table+lerp path
#define SH    392     // f16 row stride (halves)
#define SF    164     // f32 row stride (floats), 656B, 16B-aligned
#define TBL   2048    // table nodes over u in [-8,8), step 1/128

// dynamic smem (bytes):
//   [0,16384)      float2 tbl[2048]  (sigmoid value, centered slope/idx-unit)
//   [16384,28928)  half xh[16][392]
//   [28928,41472)  half wh[16][392]
//   [41472,51968)  float xf[16][164]  (x pre-scaled by 128)
//   [51968,62464)  float wf[16][164]
#define SMEM_BYTES 62464

// scratch: S[i][b][j] = sum_k sigmoid(x[i,j,k]*W[b,j,k])
__device__ float g_S[BATCH * OUT * MB];

__device__ __forceinline__ __half2 tanh_h2(__half2 v) {
    unsigned r, a = *(unsigned*)&v;
    asm("tanh.approx.f16x2 %0, %1;" : "=r"(r) : "r"(a));
    return *(__half2*)&r;
}
__device__ __forceinline__ float tanh_f32a(float t) {
    float r;
    asm("tanh.approx.f32 %0, %1;" : "=f"(r) : "f"(t));
    return r;
}

// sigmoid via table + linear correction. p = 128*x*w (x pre-scaled).
// magic 2^23 rounding gives node index + exact fractional residual.
__device__ __forceinline__ float tsig(const float2* __restrict__ tbl,
                                      float xs, float w) {
    const float C = 8389632.0f;               // 2^23 + 1024
    float p = xs * w;
    p = fminf(fmaxf(p, -1023.0f), 1023.0f);   // u in [-7.99, 7.99]
    float f = p + C;                          // RN -> round(p) + C
    float t = f - C;                          // = round(p), exact
    float frac = p - t;                       // [-0.5, 0.5], exact
    float2 e = tbl[__float_as_int(f) & 0x7FF];
    return fmaf(frac, e.y, e.x);
}

// One CTA = (16 i x 16 b) tile of ONE branch j.
// k<384: sigmoid = 0.5 + 0.5*tanh(u/2) via MUFU f16x2 (r4 proven body).
// k>=384: sigmoid via 2048-node value+slope table (lerp err ~8e-7).
__global__ __launch_bounds__(256) void dnm_main_kernel(
    const float* __restrict__ x,
    const float* __restrict__ w)
{
    extern __shared__ char dsm[];
    float2* tbl = (float2*)dsm;
    __half* xh  = (__half*)(dsm + 16384);
    __half* wh  = (__half*)(dsm + 28928);
    float*  xf  = (float*)(dsm + 41472);
    float*  wf  = (float*)(dsm + 51968);

    const int tid = threadIdx.x;
    const int tx  = tid & 15;
    const int ty  = tid >> 4;
    const int i0  = blockIdx.x * TI;
    const int b0  = blockIdx.y * TB;
    const int j   = blockIdx.z;        // 1024 CTAs total

    // ---- fill table: node i -> u = (i-1024)/128; centered slope ----
    {
        const float is = 1.0f / 128.0f;
        #pragma unroll
        for (int t8 = 0; t8 < TBL / 256; ++t8) {
            int i = t8 * 256 + tid;
            float u  = (float)(i - 1024) * is;
            float v0 = fmaf(0.5f, tanh_f32a(0.5f * u), 0.5f);
            float vp = fmaf(0.5f, tanh_f32a(0.5f * (u + is)), 0.5f);
            float vm = fmaf(0.5f, tanh_f32a(0.5f * (u - is)), 0.5f);
            tbl[i] = make_float2(v0, 0.5f * (vp - vm));
        }
    }

    // ---- tile loads: k<384 -> f16 (x*0.5); k>=384 -> f32 (x*128) ----
    #pragma unroll
    for (int it = 0; it < (TI * KMH) / (4 * 256); ++it) {   // 6 iters
        int idx = it * 256 + tid;
        int r = idx / 96, c = (idx % 96) << 2;              // 96 float4/row
        float4 v = *(const float4*)&x[((size_t)(i0 + r) * MB + j) * INS + c];
        *(__half2*)&xh[r * SH + c]     = __floats2half2_rn(0.5f * v.x, 0.5f * v.y);
        *(__half2*)&xh[r * SH + c + 2] = __floats2half2_rn(0.5f * v.z, 0.5f * v.w);
    }
    #pragma unroll
    for (int it = 0; it < (TB * KMH) / (4 * 256); ++it) {
        int idx = it * 256 + tid;
        int r = idx / 96, c = (idx % 96) << 2;
        float4 v = *(const float4*)&w[((size_t)(b0 + r) * MB + j) * INS + c];
        *(__half2*)&wh[r * SH + c]     = __floats2half2_rn(v.x, v.y);
        *(__half2*)&wh[r * SH + c + 2] = __floats2half2_rn(v.z, v.w);
    }
    #pragma unroll
    for (int it = 0; it < (TI * KTB) / (4 * 256); ++it) {   // 2 iters
        int idx = it * 256 + tid;
        int r = idx >> 5, c = (idx & 31) << 2;              // 32 float4/row
        float4 v = *(const float4*)&x[((size_t)(i0 + r) * MB + j) * INS + KMH + c];
        xf[r * SF + c + 0] = 128.0f * v.x; xf[r * SF + c + 1] = 128.0f * v.y;
        xf[r * SF + c + 2] = 128.0f * v.z; xf[r * SF + c + 3] = 128.0f * v.w;
    }
    #pragma unroll
    for (int it = 0; it < (TB * KTB) / (4 * 256); ++it) {
        int idx = it * 256 + tid;
        int r = idx >> 5, c = (idx & 31) << 2;
        float4 v = *(const float4*)&w[((size_t)(b0 + r) * MB + j) * INS + KMH + c];
        wf[r * SF + c + 0] = v.x; wf[r * SF + c + 1] = v.y;
        wf[r * SF + c + 2] = v.z; wf[r * SF + c + 3] = v.w;
    }
    __syncthreads();

    // ---- phase 1: MUFU segment (r4 proven body), k < 384 ----
    float accM0 = 0.0f, accM1 = 0.0f;
    {
        const __half* xr = xh + tx * SH;
        const __half* wr = wh + ty * SH;
        #pragma unroll 16
        for (int k = 0; k < KMH; k += 4) {
            uint2 xv = *(const uint2*)&xr[k];
            uint2 wv = *(const uint2*)&wr[k];
            __half2 t01 = __hmul2(*(__half2*)&xv.x, *(__half2*)&wv.x);
            __half2 t23 = __hmul2(*(__half2*)&xv.y, *(__half2*)&wv.y);
            __half2 h01 = tanh_h2(t01);
            __half2 h23 = tanh_h2(t23);
            __half2 s   = __hadd2(h01, h23);
            accM0 += __low2float(s);
            accM1 += __high2float(s);
        }
    }

    // ---- phase 2: table segment, k in [384,512) ----
    float accT0 = 0.0f, accT1 = 0.0f;
    {
        const float* xfr = xf + tx * SF;
        const float* wfr = wf + ty * SF;
        #pragma unroll 8
        for (int k = 0; k < KTB; k += 4) {
            float4 xv = *(const float4*)&xfr[k];
            float4 wv = *(const float4*)&wfr[k];
            accT0 += tsig(tbl, xv.x, wv.x);
            accT1 += tsig(tbl, xv.y, wv.y);
            accT0 += tsig(tbl, xv.z, wv.z);
            accT1 += tsig(tbl, xv.w, wv.w);
        }
    }

    // S = [0.5*sum tanh + 192] (384 MUFU elems) + sum sigmoid (128 table elems)
    float S = fmaf(0.5f, accM0 + accM1, 0.5f * (float)KMH) + (accT0 + accT1);
    g_S[((size_t)(i0 + tx) * OUT + (b0 + ty)) * MB + j] = S;
}

// Per-row normalize with fused product-of-branches (r4 proven version).
__global__ __launch_bounds__(OUT) void dnm_norm_kernel(float* __restrict__ out)
{
    const int i = blockIdx.x;
    const int b = threadIdx.x;

    const float* sp = &g_S[((size_t)i * OUT + b) * MB];
    float4 a = *(const float4*)sp;
    float4 c = *(const float4*)(sp + 4);
    float v = ((a.x * a.y) * (a.z * a.w)) * ((c.x * c.y) * (c.z * c.w));

    // v ~ 256^8 = 2^64 -> scale before squaring (stats are scale-invariant)
    float vs = v * 0x1p-64f;

    float s1 = vs, s2 = vs * vs;
    #pragma unroll
    for (int off = 16; off > 0; off >>= 1) {
        s1 += __shfl_xor_sync(0xffffffffu, s1, off);
        s2 += __shfl_xor_sync(0xffffffffu, s2, off);
    }
    __shared__ float r1[8], r2[8];
    if ((b & 31) == 0) { r1[b >> 5] = s1; r2[b >> 5] = s2; }
    __syncthreads();

    float total = 0.0f, sq = 0.0f;
    #pragma unroll
    for (int q = 0; q < 8; ++q) { total += r1[q]; sq += r2[q]; }

    float inv = 1.0f / total;
    float zn  = vs * inv;
    float var = (sq * inv * inv - 1.0f / 256.0f) * (1.0f / 255.0f);
    out[(size_t)i * OUT + b] = (zn - 1.0f / 256.0f) * rsqrtf(var);
}

extern "C" void kernel_launch(void* const* d_in, const int* in_sizes, int n_in,
                              void* d_out, int out_size)
{
    const float* x = (const float*)d_in[0];   // (128, 8, 512)
    const float* w = (const float*)d_in[1];   // (256, 8, 512)
    float* z = (float*)d_out;                 // (128, 256)

    cudaFuncSetAttribute(dnm_main_kernel,
                         cudaFuncAttributeMaxDynamicSharedMemorySize, SMEM_BYTES);

    dim3 grid(BATCH / TI, OUT / TB, MB);      // (8, 16, 8) = 1024 CTAs
    dnm_main_kernel<<<grid, 256, SMEM_BYTES>>>(x, w);
    dnm_norm_kernel<<<BATCH, OUT>>>(z);
}